// round 6
// baseline (speedup 1.0000x reference)
#include <cuda_runtime.h>
#include <math.h>

#define H 1024
#define L 128
#define V 50257

// ---- scratch (device globals; no allocation allowed) ----
__device__ __align__(16) float g_attn_logits[L];
__device__ __align__(16) float g_with_attn[H];
__device__ __align__(16) float g_rnn_in[H];
__device__ __align__(16) float g_gh[3 * H];      // W_hh @ h0 + b_hh (hoisted)
__device__ __align__(16) float g_hnew[H];
__device__ __align__(16) float g_logits[V];
__device__ unsigned int g_max_enc;   // ordered-uint encoded max
__device__ float g_sumexp;
__device__ int g_bar;                // grid barrier counter for fused softmax

__device__ __forceinline__ float warp_sum(float v) {
#pragma unroll
    for (int o = 16; o > 0; o >>= 1) v += __shfl_xor_sync(0xffffffffu, v, o);
    return v;
}

__device__ __forceinline__ float dot4(float4 a, float4 b) {
    return a.x * b.x + a.y * b.y + a.z * b.z + a.w * b.w;
}

// encode float so unsigned compare == float compare
__device__ __forceinline__ unsigned int enc_f(float f) {
    unsigned int u = __float_as_uint(f);
    return (u & 0x80000000u) ? ~u : (u | 0x80000000u);
}
__device__ __forceinline__ float dec_f(unsigned int u) {
    return (u & 0x80000000u) ? __uint_as_float(u ^ 0x80000000u)
                             : __uint_as_float(~u);
}

// ---- K1: three independent jobs in one grid ----
//  blocks [0,128):        attn logits[l] = dot(attn_W[l], [emb[x], h0]) + attn_b[l]
//  blocks [128,128+3072): gh[r] = dot(W_hh[r], h0) + b_hh[r]      (GRU hidden side)
//  block  3200:           zero g_with_attn, reset atomics/barrier
__global__ void __launch_bounds__(256) k_front(const int* __restrict__ x,
                              const float* __restrict__ hidden,
                              const float* __restrict__ emb,
                              const float* __restrict__ attn_W,
                              const float* __restrict__ attn_b,
                              const float* __restrict__ W_hh,
                              const float* __restrict__ b_hh) {
    int b = blockIdx.x;
    int t = threadIdx.x;         // 0..255
    if (b == 3200) {
        *(float4*)(g_with_attn + t * 4) = make_float4(0.f, 0.f, 0.f, 0.f);
        if (t == 0) { g_max_enc = 0u; g_sumexp = 0.f; g_bar = 0; }
        return;
    }
    __shared__ float s[8];
    if (b < 128) {
        int l = b;
        const float* erow = emb + (long long)x[0] * H;
        const float* wrow = attn_W + (long long)l * 2 * H;
        int j = t * 4;
        float4 w0 = __ldcs((const float4*)(wrow + j));
        float4 w1 = __ldcs((const float4*)(wrow + H + j));
        float4 c0 = *(const float4*)(erow + j);
        float4 c1 = *(const float4*)(hidden + j);
        float acc = dot4(w0, c0) + dot4(w1, c1);
        acc = warp_sum(acc);
        if ((t & 31) == 0) s[t >> 5] = acc;
        __syncthreads();
        if (t < 8) {
            float v = s[t];
#pragma unroll
            for (int o = 4; o > 0; o >>= 1) v += __shfl_xor_sync(0xffu, v, o);
            if (t == 0) g_attn_logits[l] = v + attn_b[l];
        }
    } else {
        int r = b - 128;             // 0..3071
        const float* wrow = W_hh + (long long)r * H;
        int j = t * 4;
        float4 w0 = __ldcs((const float4*)(wrow + j));
        float4 c0 = *(const float4*)(hidden + j);
        float acc = dot4(w0, c0);
        acc = warp_sum(acc);
        if ((t & 31) == 0) s[t >> 5] = acc;
        __syncthreads();
        if (t < 8) {
            float v = s[t];
#pragma unroll
            for (int o = 4; o > 0; o >>= 1) v += __shfl_xor_sync(0xffu, v, o);
            if (t == 0) g_gh[r] = v + b_hh[r];
        }
    }
}

// ---- K2: with_attn. Each block recomputes the 128-wide softmax (cheap),
//          then accumulates its 32-row x 256-col chunk via atomicAdd. ----
__global__ void __launch_bounds__(256) k_with_attn(const float* __restrict__ enc,
                                                   float* __restrict__ out_attn) {
    __shared__ float w[L];
    __shared__ float redm[4], reds[4];
    int t = threadIdx.x;
    if (t < L) {
        float v = g_attn_logits[t];
        float m = v;
#pragma unroll
        for (int o = 16; o > 0; o >>= 1) m = fmaxf(m, __shfl_xor_sync(0xffffffffu, m, o));
        if ((t & 31) == 0) redm[t >> 5] = m;
        __syncwarp();
        // cross-warp max via shared (4 warps among first 128 threads)
    }
    __syncthreads();
    if (t < L) {
        float v = g_attn_logits[t];
        float m4 = fmaxf(fmaxf(redm[0], redm[1]), fmaxf(redm[2], redm[3]));
        float e = expf(v - m4);
        float ssum = warp_sum(e);
        if ((t & 31) == 0) reds[t >> 5] = ssum;
        __syncwarp();
        w[t] = e;   // store numerator; normalize after total known
    }
    __syncthreads();
    float tot = reds[0] + reds[1] + reds[2] + reds[3];
    if (t < L) {
        w[t] = w[t] / tot;
        if (blockIdx.x == 0 && blockIdx.y == 0) out_attn[t] = w[t];
    }
    __syncthreads();
    int col = blockIdx.x * 256 + t;
    int l0 = blockIdx.y * 32;
    float acc0 = 0.f, acc1 = 0.f, acc2 = 0.f, acc3 = 0.f;
#pragma unroll
    for (int l = l0; l < l0 + 32; l += 4) {
        acc0 += w[l + 0] * __ldg(enc + (l + 0) * H + col);
        acc1 += w[l + 1] * __ldg(enc + (l + 1) * H + col);
        acc2 += w[l + 2] * __ldg(enc + (l + 2) * H + col);
        acc3 += w[l + 3] * __ldg(enc + (l + 3) * H + col);
    }
    atomicAdd(&g_with_attn[col], (acc0 + acc1) + (acc2 + acc3));
}

// ---- K3: rnn_in[i] = relu(dot(comb_W[i], [emb[x], with_attn]) + comb_b[i]) ----
// block per row; lane-contiguous float4 (round-3 best shape)
__global__ void __launch_bounds__(256) k_rnn_in(const int* __restrict__ x,
                                                const float* __restrict__ emb,
                                                const float* __restrict__ comb_W,
                                                const float* __restrict__ comb_b) {
    int row = blockIdx.x;        // 0..1023
    int t = threadIdx.x;         // 0..255
    const float* erow = emb + (long long)x[0] * H;
    const float* wrow = comb_W + (long long)row * 2 * H;
    int j = t * 4;
    float4 w0 = __ldcs((const float4*)(wrow + j));
    float4 c0 = *(const float4*)(erow + j);
    float4 w1 = __ldcs((const float4*)(wrow + H + j));
    float4 c1 = *(const float4*)(g_with_attn + j);
    float acc = dot4(w0, c0) + dot4(w1, c1);
    acc = warp_sum(acc);
    __shared__ float s[8];
    if ((t & 31) == 0) s[t >> 5] = acc;
    __syncthreads();
    if (t < 8) {
        float v = s[t];
#pragma unroll
        for (int o = 4; o > 0; o >>= 1) v += __shfl_xor_sync(0xffu, v, o);
        if (t == 0) g_rnn_in[row] = fmaxf(v + comb_b[row], 0.f);
    }
}

// ---- K4: GRU input side + combine. block i: 6 warps = 3 gate dots x 2 halves ----
__global__ void __launch_bounds__(192) k_gru(const float* __restrict__ hidden,
                                             const float* __restrict__ W_ih,
                                             const float* __restrict__ b_ih,
                                             float* __restrict__ out_h) {
    int i = blockIdx.x;              // hidden index 0..1023
    int w = threadIdx.x >> 5;        // 0..5
    int lane = threadIdx.x & 31;
    int g = w >> 1;                  // gate 0..2
    int half = w & 1;                // which 512-col half
    const float* row = W_ih + (long long)(g * H + i) * H;
    int base = half * 512;
    float4 a[4], bv[4];
#pragma unroll
    for (int k = 0; k < 4; k++) {
        int j = base + k * 128 + lane * 4;
        a[k] = __ldcs((const float4*)(row + j));
        bv[k] = *(const float4*)(g_rnn_in + j);
    }
    float acc = 0.f;
#pragma unroll
    for (int k = 0; k < 4; k++) acc += dot4(a[k], bv[k]);
    acc = warp_sum(acc);
    __shared__ float s[6];
    if (lane == 0) s[w] = acc;
    __syncthreads();
    if (threadIdx.x == 0) {
        float gx_r = s[0] + s[1] + b_ih[0 * H + i];
        float gx_z = s[2] + s[3] + b_ih[1 * H + i];
        float gx_n = s[4] + s[5] + b_ih[2 * H + i];
        float gh_r = g_gh[0 * H + i];
        float gh_z = g_gh[1 * H + i];
        float gh_n = g_gh[2 * H + i];
        float r = 1.f / (1.f + expf(-(gx_r + gh_r)));
        float z = 1.f / (1.f + expf(-(gx_z + gh_z)));
        float n = tanhf(gx_n + r * gh_n);
        float h = (1.f - z) * n + z * hidden[i];
        g_hnew[i] = h;
        out_h[i] = h;
    }
}

// ---- K5: big vocab GEMV. warp per 2 rows; all 16 loads batched for MLP ----
__global__ void __launch_bounds__(256, 2) k_logits(const float* __restrict__ out_W,
                                                   const float* __restrict__ out_b) {
    int lane = threadIdx.x & 31;
    int warp = (blockIdx.x * blockDim.x + threadIdx.x) >> 5;
    int nwarps = (gridDim.x * blockDim.x) >> 5;
    float4 h[8];
#pragma unroll
    for (int k = 0; k < 8; k++)
        h[k] = *(const float4*)(g_hnew + k * 128 + lane * 4);
    float lmax = -INFINITY;
    for (int v0 = warp * 2; v0 < V - 1; v0 += nwarps * 2) {
        const float* row0 = out_W + (long long)v0 * H + lane * 4;
        const float* row1 = row0 + H;
        float4 a0[8], a1[8];
#pragma unroll
        for (int k = 0; k < 8; k++) a0[k] = __ldcs((const float4*)(row0 + k * 128));
#pragma unroll
        for (int k = 0; k < 8; k++) a1[k] = __ldcs((const float4*)(row1 + k * 128));
        float acc0 = 0.f, acc1 = 0.f;
#pragma unroll
        for (int k = 0; k < 8; k++) {
            acc0 += dot4(a0[k], h[k]);
            acc1 += dot4(a1[k], h[k]);
        }
        acc0 = warp_sum(acc0);
        acc1 = warp_sum(acc1);
        if (lane == 0) {
            float lg0 = acc0 + out_b[v0];
            float lg1 = acc1 + out_b[v0 + 1];
            g_logits[v0] = lg0;
            g_logits[v0 + 1] = lg1;
            lmax = fmaxf(lmax, fmaxf(lg0, lg1));
        }
    }
    // tail: last row (V odd) handled by warp 0
    if (warp == 0) {
        int v = V - 1;
        const float* row = out_W + (long long)v * H + lane * 4;
        float acc = 0.f;
#pragma unroll
        for (int k = 0; k < 8; k++)
            acc += dot4(__ldcs((const float4*)(row + k * 128)), h[k]);
        acc = warp_sum(acc);
        if (lane == 0) {
            float lg = acc + out_b[v];
            g_logits[v] = lg;
            lmax = fmaxf(lmax, lg);
        }
    }
    if (lane == 0 && lmax > -INFINITY) {
        atomicMax(&g_max_enc, enc_f(lmax));
    }
}

// ---- K6: fused log-softmax epilogue: sumexp + grid barrier + writeout ----
// 256 blocks of 256 threads: all resident simultaneously -> spin barrier safe.
__global__ void __launch_bounds__(256) k_logsoftmax(float* __restrict__ out) {
    float gmax = dec_f(g_max_enc);
    int idx = blockIdx.x * blockDim.x + threadIdx.x;
    int stride = gridDim.x * blockDim.x;
    float s = 0.f;
    for (int v = idx; v < V; v += stride) s += expf(g_logits[v] - gmax);
    s = warp_sum(s);
    __shared__ float red[8];
    if ((threadIdx.x & 31) == 0) red[threadIdx.x >> 5] = s;
    __syncthreads();
    if (threadIdx.x == 0) {
        float t = 0.f;
#pragma unroll
        for (int i = 0; i < 8; i++) t += red[i];
        atomicAdd(&g_sumexp, t);
        __threadfence();
        atomicAdd(&g_bar, 1);
        // spin until all blocks have contributed
        while (atomicAdd(&g_bar, 0) < (int)gridDim.x) { }
    }
    __syncthreads();
    float lse = gmax + logf(g_sumexp);
    for (int v = idx; v < V; v += stride) out[v] = g_logits[v] - lse;
}

extern "C" void kernel_launch(void* const* d_in, const int* in_sizes, int n_in,
                              void* d_out, int out_size) {
    const int*   x       = (const int*)d_in[0];
    const float* hidden  = (const float*)d_in[1];
    const float* enc     = (const float*)d_in[2];
    const float* emb     = (const float*)d_in[3];
    const float* attn_W  = (const float*)d_in[4];
    const float* attn_b  = (const float*)d_in[5];
    const float* comb_W  = (const float*)d_in[6];
    const float* comb_b  = (const float*)d_in[7];
    const float* W_ih    = (const float*)d_in[8];
    const float* W_hh    = (const float*)d_in[9];
    const float* b_ih    = (const float*)d_in[10];
    const float* b_hh    = (const float*)d_in[11];
    const float* out_W   = (const float*)d_in[12];
    const float* out_b   = (const float*)d_in[13];
    float* out = (float*)d_out;   // layout: [logp V][h_new H][attn_w L]

    k_front<<<3201, 256>>>(x, hidden, emb, attn_W, attn_b, W_hh, b_hh);
    {
        dim3 g(H / 256, 4);
        k_with_attn<<<g, 256>>>(enc, out + V + H);
    }
    k_rnn_in<<<H, 256>>>(x, emb, comb_W, comb_b);
    k_gru<<<H, 192>>>(hidden, W_ih, b_ih, out + V);
    k_logits<<<296, 256>>>(out_W, out_b);   // 2 blocks/SM on 148 SMs
    k_logsoftmax<<<256, 256>>>(out);
}